// round 1
// baseline (speedup 1.0000x reference)
#include <cuda_runtime.h>

#define N_NODES 100000
#define D 128
#define ND (N_NODES * D)
#define GROWS 64
// smem: W[128*128] + z[64*128] + red[2*8*128] floats
#define GEMM_SMEM_FLOATS (128*128 + GROWS*128 + 2048)
#define GEMM_SMEM_BYTES (GEMM_SMEM_FLOATS * 4)

__device__ float g_agg[ND];
__device__ float g_y[ND];
__device__ float g_stats[2 * D];   // [0:128) sum, [128:256) sumsq; zero-init, re-zeroed by finalize
__device__ float g_scale[D];
__device__ float g_shift[D];

// agg = (1+eps[layer]) * h   (replaces memset + folds self term)
__global__ void init_agg_k(const float* __restrict__ h, const float* __restrict__ eps, int layer) {
    float e = 1.0f + eps[layer];
    const float4* h4 = (const float4*)h;
    float4* a4 = (float4*)g_agg;
    int n4 = ND / 4;
    for (int i = blockIdx.x * blockDim.x + threadIdx.x; i < n4; i += gridDim.x * blockDim.x) {
        float4 v = h4[i];
        v.x *= e; v.y *= e; v.z *= e; v.w *= e;
        a4[i] = v;
    }
}

// one warp per edge: coalesced 512B row gather + vectorized red to agg[dst]
__global__ void scatter_k(const float* __restrict__ h, const int* __restrict__ src,
                          const int* __restrict__ dst, int nE) {
    int gt = blockIdx.x * blockDim.x + threadIdx.x;
    int e = gt >> 5;
    int lane = gt & 31;
    if (e >= nE) return;
    int s = src[e];
    int d = dst[e];
    float4 v = ((const float4*)(h + (size_t)s * D))[lane];
    float* ap = g_agg + (size_t)d * D + lane * 4;
    asm volatile("red.global.add.v4.f32 [%0], {%1,%2,%3,%4};"
                 :: "l"(ap), "f"(v.x), "f"(v.y), "f"(v.z), "f"(v.w) : "memory");
}

// y = agg @ W + b, plus BN1 column sum/sumsq accumulation
__global__ void gemm_stats_k(const float* __restrict__ W, const float* __restrict__ b) {
    extern __shared__ float sm[];
    float* Ws = sm;                       // 16384 floats
    float* zs = sm + 128 * 128;           // 8192 floats
    float* rs = sm + 128 * 128 + GROWS * 128;  // 2048 floats

    int tid = threadIdx.x;
    int row0 = blockIdx.x * GROWS;

    // load W tile (full 128x128)
    {
        float4* Ws4 = (float4*)Ws;
        const float4* W4 = (const float4*)W;
        #pragma unroll 4
        for (int i = tid; i < 128 * 128 / 4; i += 256) Ws4[i] = W4[i];
    }
    // load z tile (64 rows)
    {
        float4* zs4 = (float4*)zs;
        const float4* a4 = (const float4*)g_agg;
        #pragma unroll
        for (int i = tid; i < GROWS * 128 / 4; i += 256) {
            int r = i >> 5;
            int row = row0 + r;
            float4 v = make_float4(0.f, 0.f, 0.f, 0.f);
            if (row < N_NODES) v = a4[(size_t)row * 32 + (i & 31)];
            zs4[i] = v;
        }
    }
    __syncthreads();

    int warp = tid >> 5, lane = tid & 31;
    int c0 = lane * 4;
    float4 bb = ((const float4*)b)[lane];
    float4 acc[8];
    #pragma unroll
    for (int r = 0; r < 8; r++) acc[r] = bb;

    #pragma unroll 2
    for (int k = 0; k < 128; k += 4) {
        float4 w0 = *(float4*)&Ws[(k + 0) * 128 + c0];
        float4 w1 = *(float4*)&Ws[(k + 1) * 128 + c0];
        float4 w2 = *(float4*)&Ws[(k + 2) * 128 + c0];
        float4 w3 = *(float4*)&Ws[(k + 3) * 128 + c0];
        #pragma unroll
        for (int r = 0; r < 8; r++) {
            float4 z = *(float4*)&zs[(warp * 8 + r) * 128 + k];
            acc[r].x += z.x * w0.x + z.y * w1.x + z.z * w2.x + z.w * w3.x;
            acc[r].y += z.x * w0.y + z.y * w1.y + z.z * w2.y + z.w * w3.y;
            acc[r].z += z.x * w0.z + z.y * w1.z + z.z * w2.z + z.w * w3.z;
            acc[r].w += z.x * w0.w + z.y * w1.w + z.z * w2.w + z.w * w3.w;
        }
    }

    // store + local stats
    float4 s = make_float4(0.f, 0.f, 0.f, 0.f);
    float4 q = make_float4(0.f, 0.f, 0.f, 0.f);
    float4* y4 = (float4*)g_y;
    #pragma unroll
    for (int r = 0; r < 8; r++) {
        int row = row0 + warp * 8 + r;
        if (row < N_NODES) {
            y4[(size_t)row * 32 + lane] = acc[r];
            s.x += acc[r].x; s.y += acc[r].y; s.z += acc[r].z; s.w += acc[r].w;
            q.x += acc[r].x * acc[r].x; q.y += acc[r].y * acc[r].y;
            q.z += acc[r].z * acc[r].z; q.w += acc[r].w * acc[r].w;
        }
    }
    rs[warp * 128 + c0 + 0] = s.x; rs[warp * 128 + c0 + 1] = s.y;
    rs[warp * 128 + c0 + 2] = s.z; rs[warp * 128 + c0 + 3] = s.w;
    rs[1024 + warp * 128 + c0 + 0] = q.x; rs[1024 + warp * 128 + c0 + 1] = q.y;
    rs[1024 + warp * 128 + c0 + 2] = q.z; rs[1024 + warp * 128 + c0 + 3] = q.w;
    __syncthreads();

    int col = tid & 127;
    int so = (tid >> 7) * 1024;
    float v = 0.f;
    #pragma unroll
    for (int w = 0; w < 8; w++) v += rs[so + w * 128 + col];
    atomicAdd(&g_stats[(tid >> 7) * 128 + col], v);
}

// consume g_stats -> scale/shift, re-zero g_stats (replay-invariant)
__global__ void finalize_k(const float* __restrict__ gamma, const float* __restrict__ beta) {
    int c = threadIdx.x;
    float sum = g_stats[c];
    float sq = g_stats[128 + c];
    float mean = sum * (1.0f / N_NODES);
    float var = sq * (1.0f / N_NODES) - mean * mean;
    float scl = rsqrtf(var + 1e-5f) * gamma[c];
    g_scale[c] = scl;
    g_shift[c] = beta[c] - mean * scl;
    g_stats[c] = 0.f;
    g_stats[128 + c] = 0.f;
}

// y = relu(y*scale+shift) in place, accumulate BN2 stats
__global__ void bn_relu_stats_k() {
    __shared__ float rs[2048];
    int tid = threadIdx.x, lane = tid & 31, warp = tid >> 5;
    float4 sc = ((const float4*)g_scale)[lane];
    float4 sh = ((const float4*)g_shift)[lane];
    float4 s = make_float4(0.f, 0.f, 0.f, 0.f);
    float4 q = make_float4(0.f, 0.f, 0.f, 0.f);
    float4* y4 = (float4*)g_y;
    int n4 = ND / 4;
    for (int i = blockIdx.x * 256 + tid; i < n4; i += gridDim.x * 256) {
        float4 v = y4[i];
        v.x = fmaxf(fmaf(v.x, sc.x, sh.x), 0.f);
        v.y = fmaxf(fmaf(v.y, sc.y, sh.y), 0.f);
        v.z = fmaxf(fmaf(v.z, sc.z, sh.z), 0.f);
        v.w = fmaxf(fmaf(v.w, sc.w, sh.w), 0.f);
        y4[i] = v;
        s.x += v.x; s.y += v.y; s.z += v.z; s.w += v.w;
        q.x += v.x * v.x; q.y += v.y * v.y; q.z += v.z * v.z; q.w += v.w * v.w;
    }
    int c0 = lane * 4;
    rs[warp * 128 + c0 + 0] = s.x; rs[warp * 128 + c0 + 1] = s.y;
    rs[warp * 128 + c0 + 2] = s.z; rs[warp * 128 + c0 + 3] = s.w;
    rs[1024 + warp * 128 + c0 + 0] = q.x; rs[1024 + warp * 128 + c0 + 1] = q.y;
    rs[1024 + warp * 128 + c0 + 2] = q.z; rs[1024 + warp * 128 + c0 + 3] = q.w;
    __syncthreads();
    int col = tid & 127;
    int so = (tid >> 7) * 1024;
    float v = 0.f;
    #pragma unroll
    for (int w = 0; w < 8; w++) v += rs[so + w * 128 + col];
    atomicAdd(&g_stats[(tid >> 7) * 128 + col], v);
}

// out = relu(y*scale+shift)  -> next layer's h
__global__ void bn_relu_out_k(float* __restrict__ out) {
    int tid = threadIdx.x, lane = tid & 31;
    float4 sc = ((const float4*)g_scale)[lane];
    float4 sh = ((const float4*)g_shift)[lane];
    const float4* y4 = (const float4*)g_y;
    float4* o4 = (float4*)out;
    int n4 = ND / 4;
    for (int i = blockIdx.x * 256 + tid; i < n4; i += gridDim.x * 256) {
        float4 v = y4[i];
        v.x = fmaxf(fmaf(v.x, sc.x, sh.x), 0.f);
        v.y = fmaxf(fmaf(v.y, sc.y, sh.y), 0.f);
        v.z = fmaxf(fmaf(v.z, sc.z, sh.z), 0.f);
        v.w = fmaxf(fmaf(v.w, sc.w, sh.w), 0.f);
        o4[i] = v;
    }
}

extern "C" void kernel_launch(void* const* d_in, const int* in_sizes, int n_in,
                              void* d_out, int out_size) {
    const float* features = (const float*)d_in[0];
    const float* W   = (const float*)d_in[1];
    const float* b   = (const float*)d_in[2];
    const float* eps = (const float*)d_in[3];
    const float* g1  = (const float*)d_in[4];
    const float* be1 = (const float*)d_in[5];
    const float* g2  = (const float*)d_in[6];
    const float* be2 = (const float*)d_in[7];
    const int* src   = (const int*)d_in[8];
    const int* dst   = (const int*)d_in[9];
    int nE = in_sizes[8];
    float* out = (float*)d_out;

    static bool once = []() {
        cudaFuncSetAttribute(gemm_stats_k, cudaFuncAttributeMaxDynamicSharedMemorySize,
                             GEMM_SMEM_BYTES);
        return true;
    }();
    (void)once;

    // slab 0 = input features
    cudaMemcpyAsync(out, features, (size_t)ND * sizeof(float), cudaMemcpyDeviceToDevice);

    for (int i = 0; i < 3; i++) {
        const float* h = out + (size_t)i * ND;
        float* hn = out + (size_t)(i + 1) * ND;
        init_agg_k<<<1184, 256>>>(h, eps, i);
        int scatter_blocks = (int)(((long long)nE * 32 + 255) / 256);
        scatter_k<<<scatter_blocks, 256>>>(h, src, dst, nE);
        gemm_stats_k<<<(N_NODES + GROWS - 1) / GROWS, 256, GEMM_SMEM_BYTES>>>(W + (size_t)i * D * D, b + (size_t)i * D);
        finalize_k<<<1, 128>>>(g1 + i * D, be1 + i * D);
        bn_relu_stats_k<<<1184, 256>>>();
        finalize_k<<<1, 128>>>(g2 + i * D, be2 + i * D);
        bn_relu_out_k<<<1184, 256>>>(hn);
    }
}

// round 2
// speedup vs baseline: 1.1351x; 1.1351x over previous
#include <cuda_runtime.h>

#define N_NODES 100000
#define N_EDGES_MAX 1600000
#define D 128
#define ND (N_NODES * D)
#define GROWS 64
// smem: W[128*128] + z[64*128] + red[2*8*128] floats
#define GEMM_SMEM_FLOATS (128*128 + GROWS*128 + 2048)
#define GEMM_SMEM_BYTES (GEMM_SMEM_FLOATS * 4)

__device__ float g_y[ND];
__device__ float g_stats[2 * D];   // zero-init; re-zeroed by finalize each use
__device__ float g_scale[D];
__device__ float g_shift[D];
__device__ int g_deg[N_NODES];
__device__ int g_off[N_NODES + 1];
__device__ int g_cur[N_NODES];
__device__ int g_eidx[N_EDGES_MAX];

// ---------------- CSR build (once per launch) ----------------
__global__ void zero_deg_k() {
    for (int i = blockIdx.x * blockDim.x + threadIdx.x; i < N_NODES; i += gridDim.x * blockDim.x)
        g_deg[i] = 0;
}

__global__ void hist_k(const int* __restrict__ dst, int nE) {
    for (int e = blockIdx.x * blockDim.x + threadIdx.x; e < nE; e += gridDim.x * blockDim.x)
        atomicAdd(&g_deg[dst[e]], 1);
}

__global__ void scan_k(int nE) {
    __shared__ int sm[1024];
    const int t = threadIdx.x;
    const int CH = (N_NODES + 1023) / 1024;  // 98
    int base = t * CH;
    int s = 0;
    for (int i = 0; i < CH; i++) {
        int idx = base + i;
        if (idx < N_NODES) s += g_deg[idx];
    }
    sm[t] = s;
    __syncthreads();
    for (int d = 1; d < 1024; d <<= 1) {
        int v = (t >= d) ? sm[t - d] : 0;
        __syncthreads();
        sm[t] += v;
        __syncthreads();
    }
    int off = sm[t] - s;  // exclusive
    for (int i = 0; i < CH; i++) {
        int idx = base + i;
        if (idx < N_NODES) {
            g_off[idx] = off;
            g_cur[idx] = off;
            off += g_deg[idx];
        }
    }
    if (t == 1023) g_off[N_NODES] = nE;
}

__global__ void fill_k(const int* __restrict__ src, const int* __restrict__ dst, int nE) {
    for (int e = blockIdx.x * blockDim.x + threadIdx.x; e < nE; e += gridDim.x * blockDim.x) {
        int p = atomicAdd(&g_cur[dst[e]], 1);
        g_eidx[p] = src[e];
    }
}

// ---------------- fused gather + GEMM + BN1 stats ----------------
// z = (1+eps)*h + sum_{u in N(v)} h[u]   (built in smem via CSR gather)
// y = z @ W + b                          (written to g_y)
// BN1 column sum/sumsq accumulated into g_stats
__global__ void gather_gemm_stats_k(const float* __restrict__ h, const float* __restrict__ W,
                                    const float* __restrict__ b, const float* __restrict__ eps,
                                    int layer) {
    extern __shared__ float sm[];
    float* Ws = sm;                            // 16384 floats
    float* zs = sm + 128 * 128;                // 8192 floats
    float* rs = sm + 128 * 128 + GROWS * 128;  // 2048 floats

    const int tid = threadIdx.x;
    const int warp = tid >> 5, lane = tid & 31;
    const int row0 = blockIdx.x * GROWS;
    const float e1 = 1.0f + __ldg(&eps[layer]);

    // load W tile (full 128x128)
    {
        float4* Ws4 = (float4*)Ws;
        const float4* W4 = (const float4*)W;
        #pragma unroll 4
        for (int i = tid; i < 128 * 128 / 4; i += 256) Ws4[i] = W4[i];
    }

    // gather phase: each warp builds 8 rows of Z in smem
    {
        const float4* hp = (const float4*)h;
        float4* zs4 = (float4*)zs;
        #pragma unroll
        for (int r = 0; r < 8; r++) {
            int wr = warp * 8 + r;
            int row = row0 + wr;
            float4 acc = make_float4(0.f, 0.f, 0.f, 0.f);
            if (row < N_NODES) {
                float4 v = hp[(size_t)row * 32 + lane];
                acc.x = e1 * v.x; acc.y = e1 * v.y; acc.z = e1 * v.z; acc.w = e1 * v.w;
                int start = g_off[row];
                int deg = g_off[row + 1] - start;
                for (int basee = 0; basee < deg; basee += 32) {
                    int m = deg - basee; if (m > 32) m = 32;
                    int idx = 0;
                    if (lane < m) idx = g_eidx[start + basee + lane];
                    int l = 0;
                    for (; l + 4 <= m; l += 4) {
                        int s0 = __shfl_sync(0xffffffffu, idx, l);
                        int s1 = __shfl_sync(0xffffffffu, idx, l + 1);
                        int s2 = __shfl_sync(0xffffffffu, idx, l + 2);
                        int s3 = __shfl_sync(0xffffffffu, idx, l + 3);
                        float4 a0 = hp[(size_t)s0 * 32 + lane];
                        float4 a1 = hp[(size_t)s1 * 32 + lane];
                        float4 a2 = hp[(size_t)s2 * 32 + lane];
                        float4 a3 = hp[(size_t)s3 * 32 + lane];
                        acc.x += (a0.x + a1.x) + (a2.x + a3.x);
                        acc.y += (a0.y + a1.y) + (a2.y + a3.y);
                        acc.z += (a0.z + a1.z) + (a2.z + a3.z);
                        acc.w += (a0.w + a1.w) + (a2.w + a3.w);
                    }
                    for (; l < m; l++) {
                        int s0 = __shfl_sync(0xffffffffu, idx, l);
                        float4 a0 = hp[(size_t)s0 * 32 + lane];
                        acc.x += a0.x; acc.y += a0.y; acc.z += a0.z; acc.w += a0.w;
                    }
                }
            }
            zs4[wr * 32 + lane] = acc;
        }
    }
    __syncthreads();

    // GEMM phase
    const int c0 = lane * 4;
    float4 bb = ((const float4*)b)[lane];
    float4 acc[8];
    #pragma unroll
    for (int r = 0; r < 8; r++) acc[r] = bb;

    #pragma unroll 2
    for (int k = 0; k < 128; k += 4) {
        float4 w0 = *(float4*)&Ws[(k + 0) * 128 + c0];
        float4 w1 = *(float4*)&Ws[(k + 1) * 128 + c0];
        float4 w2 = *(float4*)&Ws[(k + 2) * 128 + c0];
        float4 w3 = *(float4*)&Ws[(k + 3) * 128 + c0];
        #pragma unroll
        for (int r = 0; r < 8; r++) {
            float4 z = *(float4*)&zs[(warp * 8 + r) * 128 + k];
            acc[r].x += z.x * w0.x + z.y * w1.x + z.z * w2.x + z.w * w3.x;
            acc[r].y += z.x * w0.y + z.y * w1.y + z.z * w2.y + z.w * w3.y;
            acc[r].z += z.x * w0.z + z.y * w1.z + z.z * w2.z + z.w * w3.z;
            acc[r].w += z.x * w0.w + z.y * w1.w + z.z * w2.w + z.w * w3.w;
        }
    }

    // store + local BN1 stats
    float4 s = make_float4(0.f, 0.f, 0.f, 0.f);
    float4 q = make_float4(0.f, 0.f, 0.f, 0.f);
    float4* y4 = (float4*)g_y;
    #pragma unroll
    for (int r = 0; r < 8; r++) {
        int row = row0 + warp * 8 + r;
        if (row < N_NODES) {
            y4[(size_t)row * 32 + lane] = acc[r];
            s.x += acc[r].x; s.y += acc[r].y; s.z += acc[r].z; s.w += acc[r].w;
            q.x += acc[r].x * acc[r].x; q.y += acc[r].y * acc[r].y;
            q.z += acc[r].z * acc[r].z; q.w += acc[r].w * acc[r].w;
        }
    }
    rs[warp * 128 + c0 + 0] = s.x; rs[warp * 128 + c0 + 1] = s.y;
    rs[warp * 128 + c0 + 2] = s.z; rs[warp * 128 + c0 + 3] = s.w;
    rs[1024 + warp * 128 + c0 + 0] = q.x; rs[1024 + warp * 128 + c0 + 1] = q.y;
    rs[1024 + warp * 128 + c0 + 2] = q.z; rs[1024 + warp * 128 + c0 + 3] = q.w;
    __syncthreads();

    int col = tid & 127;
    int so = (tid >> 7) * 1024;
    float v = 0.f;
    #pragma unroll
    for (int w = 0; w < 8; w++) v += rs[so + w * 128 + col];
    atomicAdd(&g_stats[(tid >> 7) * 128 + col], v);
}

// consume g_stats -> scale/shift, re-zero g_stats (replay-invariant)
__global__ void finalize_k(const float* __restrict__ gamma, const float* __restrict__ beta) {
    int c = threadIdx.x;
    float sum = g_stats[c];
    float sq = g_stats[128 + c];
    float mean = sum * (1.0f / N_NODES);
    float var = sq * (1.0f / N_NODES) - mean * mean;
    float scl = rsqrtf(var + 1e-5f) * gamma[c];
    g_scale[c] = scl;
    g_shift[c] = beta[c] - mean * scl;
    g_stats[c] = 0.f;
    g_stats[128 + c] = 0.f;
}

// y = relu(y*scale+shift) in place, accumulate BN2 stats
__global__ void bn_relu_stats_k() {
    __shared__ float rs[2048];
    int tid = threadIdx.x, lane = tid & 31, warp = tid >> 5;
    float4 sc = ((const float4*)g_scale)[lane];
    float4 sh = ((const float4*)g_shift)[lane];
    float4 s = make_float4(0.f, 0.f, 0.f, 0.f);
    float4 q = make_float4(0.f, 0.f, 0.f, 0.f);
    float4* y4 = (float4*)g_y;
    int n4 = ND / 4;
    for (int i = blockIdx.x * 256 + tid; i < n4; i += gridDim.x * 256) {
        float4 v = y4[i];
        v.x = fmaxf(fmaf(v.x, sc.x, sh.x), 0.f);
        v.y = fmaxf(fmaf(v.y, sc.y, sh.y), 0.f);
        v.z = fmaxf(fmaf(v.z, sc.z, sh.z), 0.f);
        v.w = fmaxf(fmaf(v.w, sc.w, sh.w), 0.f);
        y4[i] = v;
        s.x += v.x; s.y += v.y; s.z += v.z; s.w += v.w;
        q.x += v.x * v.x; q.y += v.y * v.y; q.z += v.z * v.z; q.w += v.w * v.w;
    }
    int c0 = lane * 4;
    rs[warp * 128 + c0 + 0] = s.x; rs[warp * 128 + c0 + 1] = s.y;
    rs[warp * 128 + c0 + 2] = s.z; rs[warp * 128 + c0 + 3] = s.w;
    rs[1024 + warp * 128 + c0 + 0] = q.x; rs[1024 + warp * 128 + c0 + 1] = q.y;
    rs[1024 + warp * 128 + c0 + 2] = q.z; rs[1024 + warp * 128 + c0 + 3] = q.w;
    __syncthreads();
    int col = tid & 127;
    int so = (tid >> 7) * 1024;
    float v = 0.f;
    #pragma unroll
    for (int w = 0; w < 8; w++) v += rs[so + w * 128 + col];
    atomicAdd(&g_stats[(tid >> 7) * 128 + col], v);
}

// out = relu(y*scale+shift)  -> next layer's h
__global__ void bn_relu_out_k(float* __restrict__ out) {
    int tid = threadIdx.x, lane = tid & 31;
    float4 sc = ((const float4*)g_scale)[lane];
    float4 sh = ((const float4*)g_shift)[lane];
    const float4* y4 = (const float4*)g_y;
    float4* o4 = (float4*)out;
    int n4 = ND / 4;
    for (int i = blockIdx.x * 256 + tid; i < n4; i += gridDim.x * 256) {
        float4 v = y4[i];
        v.x = fmaxf(fmaf(v.x, sc.x, sh.x), 0.f);
        v.y = fmaxf(fmaf(v.y, sc.y, sh.y), 0.f);
        v.z = fmaxf(fmaf(v.z, sc.z, sh.z), 0.f);
        v.w = fmaxf(fmaf(v.w, sc.w, sh.w), 0.f);
        o4[i] = v;
    }
}

extern "C" void kernel_launch(void* const* d_in, const int* in_sizes, int n_in,
                              void* d_out, int out_size) {
    const float* features = (const float*)d_in[0];
    const float* W   = (const float*)d_in[1];
    const float* b   = (const float*)d_in[2];
    const float* eps = (const float*)d_in[3];
    const float* g1  = (const float*)d_in[4];
    const float* be1 = (const float*)d_in[5];
    const float* g2  = (const float*)d_in[6];
    const float* be2 = (const float*)d_in[7];
    const int* src   = (const int*)d_in[8];
    const int* dst   = (const int*)d_in[9];
    int nE = in_sizes[8];
    float* out = (float*)d_out;

    static bool once = []() {
        cudaFuncSetAttribute(gather_gemm_stats_k, cudaFuncAttributeMaxDynamicSharedMemorySize,
                             GEMM_SMEM_BYTES);
        return true;
    }();
    (void)once;

    // slab 0 = input features
    cudaMemcpyAsync(out, features, (size_t)ND * sizeof(float), cudaMemcpyDeviceToDevice);

    // build CSR (dst -> list of src) once
    zero_deg_k<<<392, 256>>>();
    hist_k<<<6250, 256>>>(dst, nE);
    scan_k<<<1, 1024>>>(nE);
    fill_k<<<6250, 256>>>(src, dst, nE);

    for (int i = 0; i < 3; i++) {
        const float* h = out + (size_t)i * ND;
        float* hn = out + (size_t)(i + 1) * ND;
        gather_gemm_stats_k<<<(N_NODES + GROWS - 1) / GROWS, 256, GEMM_SMEM_BYTES>>>(
            h, W + (size_t)i * D * D, b + (size_t)i * D, eps, i);
        finalize_k<<<1, 128>>>(g1 + i * D, be1 + i * D);
        bn_relu_stats_k<<<1184, 256>>>();
        finalize_k<<<1, 128>>>(g2 + i * D, be2 + i * D);
        bn_relu_out_k<<<1184, 256>>>(hn);
    }
}